// round 12
// baseline (speedup 1.0000x reference)
#include <cuda_runtime.h>
#include <cstdint>

// Problem constants
#define HID   1024
#define NHEAD 16
#define DKDIM 64
#define SEQ   2048
#define BATCH 2
#define MROWS (BATCH * SEQ)      // 4096
#define HEADSZ (SEQ * DKDIM)     // 131072 floats per (b,h) head

// Scratch (allocation-free rule: __device__ globals)
__device__ float g_Q[MROWS * HID];   // head-major [B*NH][SEQ][DK]
__device__ float g_K[MROWS * HID];
__device__ float g_V[MROWS * HID];
__device__ float g_M[MROWS * HID];   // merged attention output [MROWS][HID]

// ---------------------------------------------------------------------------
// SGEMM: C[M,N] = A[M,K=1024] * W[1024,N] + bias
// 128x128 tile, GBK=16, register-staged double buffer, 1 sync per chunk.
// B fragments at {tx*4, 64+tx*4}: stride-4 => conflict-free LDS.128.
// A loader: warp spans 32 rows => conflict-free transposing STS.32.
// ---------------------------------------------------------------------------
#define GBM 128
#define GBN 128
#define GBK 16
#define NKCH (HID / GBK)   // 64

template<bool HEAD_MAJOR>
__device__ __forceinline__ void sgemm_tile(const float* __restrict__ A,
                                           const float* __restrict__ W,
                                           const float* __restrict__ bias,
                                           float* __restrict__ out, int N) {
    __shared__ float As[2][GBK][GBM];   // 16 KB
    __shared__ float Bs[2][GBK][GBN];   // 16 KB
    const int tid = threadIdx.x;
    const int tx = tid & 15, ty = tid >> 4;
    const int row0 = blockIdx.y * GBM;
    const int col0 = blockIdx.x * GBN;

    // A loader: row = tid&127 (warp = 32 distinct rows), k8 = (tid>>7)*8
    const int a_row = tid & 127;
    const int a_k8  = (tid >> 7) * 8;
    // B loader: k-row = tid/16 (0..15), n-offsets {b_n4, 64+b_n4}
    const int b_k  = tid >> 4;
    const int b_n4 = (tid & 15) * 4;

    const float* Aptr = A + (size_t)(row0 + a_row) * HID + a_k8;
    const float* Wptr = W + col0 + b_n4;   // + k*N per chunk

    float acc[8][8];
#pragma unroll
    for (int i = 0; i < 8; i++)
#pragma unroll
        for (int j = 0; j < 8; j++) acc[i][j] = 0.f;

    // preamble: chunk 0 -> smem[0]
    {
        float4 ra0 = *(const float4*)(Aptr + 0);
        float4 ra1 = *(const float4*)(Aptr + 4);
        float4 rb0 = *(const float4*)(Wptr + (size_t)b_k * N);
        float4 rb1 = *(const float4*)(Wptr + (size_t)b_k * N + 64);
        As[0][a_k8 + 0][a_row] = ra0.x; As[0][a_k8 + 1][a_row] = ra0.y;
        As[0][a_k8 + 2][a_row] = ra0.z; As[0][a_k8 + 3][a_row] = ra0.w;
        As[0][a_k8 + 4][a_row] = ra1.x; As[0][a_k8 + 5][a_row] = ra1.y;
        As[0][a_k8 + 6][a_row] = ra1.z; As[0][a_k8 + 7][a_row] = ra1.w;
        *(float4*)&Bs[0][b_k][b_n4]      = rb0;
        *(float4*)&Bs[0][b_k][b_n4 + 64] = rb1;
    }
    __syncthreads();

    for (int c = 0; c < NKCH; c++) {
        const int buf = c & 1;
        float4 ra0, ra1, rb0, rb1;
        const bool more = (c + 1 < NKCH);
        if (more) {
            const int k0 = (c + 1) * GBK;
            ra0 = *(const float4*)(Aptr + k0);
            ra1 = *(const float4*)(Aptr + k0 + 4);
            rb0 = *(const float4*)(Wptr + (size_t)(k0 + b_k) * N);
            rb1 = *(const float4*)(Wptr + (size_t)(k0 + b_k) * N + 64);
        }
#pragma unroll
        for (int k = 0; k < GBK; k++) {
            float4 a0 = *(const float4*)&As[buf][k][ty * 8];
            float4 a1 = *(const float4*)&As[buf][k][ty * 8 + 4];
            float4 b0 = *(const float4*)&Bs[buf][k][tx * 4];
            float4 b1 = *(const float4*)&Bs[buf][k][64 + tx * 4];
            float ra[8] = {a0.x, a0.y, a0.z, a0.w, a1.x, a1.y, a1.z, a1.w};
            float rb[8] = {b0.x, b0.y, b0.z, b0.w, b1.x, b1.y, b1.z, b1.w};
#pragma unroll
            for (int i = 0; i < 8; i++)
#pragma unroll
                for (int j = 0; j < 8; j++)
                    acc[i][j] = fmaf(ra[i], rb[j], acc[i][j]);
        }
        if (more) {
            const int nb = buf ^ 1;
            As[nb][a_k8 + 0][a_row] = ra0.x; As[nb][a_k8 + 1][a_row] = ra0.y;
            As[nb][a_k8 + 2][a_row] = ra0.z; As[nb][a_k8 + 3][a_row] = ra0.w;
            As[nb][a_k8 + 4][a_row] = ra1.x; As[nb][a_k8 + 5][a_row] = ra1.y;
            As[nb][a_k8 + 6][a_row] = ra1.z; As[nb][a_k8 + 7][a_row] = ra1.w;
            *(float4*)&Bs[nb][b_k][b_n4]      = rb0;
            *(float4*)&Bs[nb][b_k][b_n4 + 64] = rb1;
            __syncthreads();
        }
    }

#pragma unroll
    for (int i = 0; i < 8; i++) {
        int m = row0 + ty * 8 + i;
        int b = m >> 11, s = m & 2047;   // SEQ = 2048
#pragma unroll
        for (int j = 0; j < 8; j++) {
            int n = col0 + ((j < 4) ? (tx * 4 + j) : (64 + tx * 4 + j - 4));
            float v = acc[i][j] + bias[n];
            if (HEAD_MAJOR) {
                int hh = n >> 6, d = n & 63;   // DK = 64
                out[((size_t)((b << 4) + hh) << 17) + ((size_t)s << 6) + d] = v;
            } else {
                out[(size_t)m * N + n] = v;
            }
        }
    }
}

__global__ __launch_bounds__(256, 2) void qkv_gemm_kernel(
    const float* q, const float* k, const float* v,
    const float* Wq, const float* bq,
    const float* Wk, const float* bk,
    const float* Wv, const float* bv) {
    const float *A, *W, *bias;
    float* out;
    if (blockIdx.z == 0)      { A = q; W = Wq; bias = bq; out = g_Q; }
    else if (blockIdx.z == 1) { A = k; W = Wk; bias = bk; out = g_K; }
    else                      { A = v; W = Wv; bias = bv; out = g_V; }
    sgemm_tile<true>(A, W, bias, out, HID);
}

__global__ __launch_bounds__(256, 2) void out_gemm_kernel(
    const float* Wo, const float* bo,
    const float* Wc, const float* bc, float* out) {
    const float *W, *bias;
    float* o;
    if (blockIdx.z == 0) { W = Wc; bias = bc; o = out; }                        // c first
    else                 { W = Wo; bias = bo; o = out + (size_t)MROWS * HID; }  // then h
    sgemm_tile<false>(g_M, W, bias, o, HID);
}

// ---------------------------------------------------------------------------
// Flash attention, 64q x 64k tiles. 256 threads = (tx=16, ty=16).
// Scores 4q x 4k in registers; softmax via shfl_xor; P through smem (U).
// Phase C blocked by 4 k-cols: float4 P + float4 V loads, 64 FMA per block.
// ---------------------------------------------------------------------------
#define PVROW(i, pp) do { \
    acc[i][0] = fmaf(pp.x, v0.x, acc[i][0]); acc[i][0] = fmaf(pp.y, v1.x, acc[i][0]); \
    acc[i][0] = fmaf(pp.z, v2.x, acc[i][0]); acc[i][0] = fmaf(pp.w, v3.x, acc[i][0]); \
    acc[i][1] = fmaf(pp.x, v0.y, acc[i][1]); acc[i][1] = fmaf(pp.y, v1.y, acc[i][1]); \
    acc[i][1] = fmaf(pp.z, v2.y, acc[i][1]); acc[i][1] = fmaf(pp.w, v3.y, acc[i][1]); \
    acc[i][2] = fmaf(pp.x, v0.z, acc[i][2]); acc[i][2] = fmaf(pp.y, v1.z, acc[i][2]); \
    acc[i][2] = fmaf(pp.z, v2.z, acc[i][2]); acc[i][2] = fmaf(pp.w, v3.z, acc[i][2]); \
    acc[i][3] = fmaf(pp.x, v0.w, acc[i][3]); acc[i][3] = fmaf(pp.y, v1.w, acc[i][3]); \
    acc[i][3] = fmaf(pp.z, v2.w, acc[i][3]); acc[i][3] = fmaf(pp.w, v3.w, acc[i][3]); \
} while (0)

__global__ __launch_bounds__(256) void attn_kernel() {
    __shared__ float QsT[64 * 64];   // [d][q]
    __shared__ float U[64 * 64];     // K^T [d][k] -> P [q][k]
    __shared__ float Vs[64 * 64];    // [k][d]

    const int bh = blockIdx.y;
    const int q0 = blockIdx.x * 64;
    const float* Qh = g_Q + (size_t)bh * HEADSZ;
    const float* Kh = g_K + (size_t)bh * HEADSZ;
    const float* Vh = g_V + (size_t)bh * HEADSZ;
    const int tid = threadIdx.x;
    const int tx = tid & 15, ty = tid >> 4;

    // Load Q transposed + scaled. idx -> (q = idx&63, d4 = (idx>>6)*4)
#pragma unroll
    for (int t = 0; t < 4; t++) {
        int idx = tid + t * 256;
        int r = idx & 63, c4 = (idx >> 6) << 2;
        float4 v = *(const float4*)(Qh + (size_t)(q0 + r) * DKDIM + c4);
        QsT[(c4 + 0) * 64 + r] = v.x * 0.125f;
        QsT[(c4 + 1) * 64 + r] = v.y * 0.125f;
        QsT[(c4 + 2) * 64 + r] = v.z * 0.125f;
        QsT[(c4 + 3) * 64 + r] = v.w * 0.125f;
    }

    float m[4], l[4], acc[4][4];
#pragma unroll
    for (int i = 0; i < 4; i++) {
        m[i] = -1e30f; l[i] = 0.f;
#pragma unroll
        for (int j = 0; j < 4; j++) acc[i][j] = 0.f;
    }

    // prefetch tile 0 into regs: K via transpose mapping, V coalesced
    float4 kreg[4], vreg[4];
#pragma unroll
    for (int t = 0; t < 4; t++) {
        int idx = tid + t * 256;
        int rk = idx & 63, ck = (idx >> 6) << 2;
        kreg[t] = *(const float4*)(Kh + (size_t)rk * DKDIM + ck);
        int rv = idx >> 4, cv = (idx & 15) << 2;
        vreg[t] = *(const float4*)(Vh + (size_t)rv * DKDIM + cv);
    }
    __syncthreads();   // QsT visible

    for (int c = 0; c < SEQ / 64; c++) {
        // store prefetched K (transposed) and V
#pragma unroll
        for (int t = 0; t < 4; t++) {
            int idx = tid + t * 256;
            int rk = idx & 63, ck = (idx >> 6) << 2;
            U[(ck + 0) * 64 + rk] = kreg[t].x;
            U[(ck + 1) * 64 + rk] = kreg[t].y;
            U[(ck + 2) * 64 + rk] = kreg[t].z;
            U[(ck + 3) * 64 + rk] = kreg[t].w;
            int rv = idx >> 4, cv = (idx & 15) << 2;
            *(float4*)(Vs + rv * 64 + cv) = vreg[t];
        }
        __syncthreads();   // S1: tiles visible

        if (c + 1 < SEQ / 64) {
            const int k0 = (c + 1) * 64;
#pragma unroll
            for (int t = 0; t < 4; t++) {
                int idx = tid + t * 256;
                int rk = idx & 63, ck = (idx >> 6) << 2;
                kreg[t] = *(const float4*)(Kh + (size_t)(k0 + rk) * DKDIM + ck);
                int rv = idx >> 4, cv = (idx & 15) << 2;
                vreg[t] = *(const float4*)(Vh + (size_t)(k0 + rv) * DKDIM + cv);
            }
        }

        // Phase A: scores (4q x 4k) in registers
        float s[4][4];
#pragma unroll
        for (int i = 0; i < 4; i++)
#pragma unroll
            for (int j = 0; j < 4; j++) s[i][j] = 0.f;
#pragma unroll 8
        for (int d = 0; d < 64; d++) {
            float4 qv = *(const float4*)(QsT + d * 64 + ty * 4);
            float4 kv = *(const float4*)(U + d * 64 + tx * 4);
            s[0][0] = fmaf(qv.x, kv.x, s[0][0]); s[0][1] = fmaf(qv.x, kv.y, s[0][1]);
            s[0][2] = fmaf(qv.x, kv.z, s[0][2]); s[0][3] = fmaf(qv.x, kv.w, s[0][3]);
            s[1][0] = fmaf(qv.y, kv.x, s[1][0]); s[1][1] = fmaf(qv.y, kv.y, s[1][1]);
            s[1][2] = fmaf(qv.y, kv.z, s[1][2]); s[1][3] = fmaf(qv.y, kv.w, s[1][3]);
            s[2][0] = fmaf(qv.z, kv.x, s[2][0]); s[2][1] = fmaf(qv.z, kv.y, s[2][1]);
            s[2][2] = fmaf(qv.z, kv.z, s[2][2]); s[2][3] = fmaf(qv.z, kv.w, s[2][3]);
            s[3][0] = fmaf(qv.w, kv.x, s[3][0]); s[3][1] = fmaf(qv.w, kv.y, s[3][1]);
            s[3][2] = fmaf(qv.w, kv.z, s[3][2]); s[3][3] = fmaf(qv.w, kv.w, s[3][3]);
        }

        // Online softmax in registers (replicated across tx via shuffles)
        float alpha[4];
#pragma unroll
        for (int i = 0; i < 4; i++) {
            float rm = fmaxf(fmaxf(s[i][0], s[i][1]), fmaxf(s[i][2], s[i][3]));
#pragma unroll
            for (int o = 8; o >= 1; o >>= 1)
                rm = fmaxf(rm, __shfl_xor_sync(0xffffffffu, rm, o));
            float mn = fmaxf(m[i], rm);
            alpha[i] = __expf(m[i] - mn);
            m[i] = mn;
            s[i][0] = __expf(s[i][0] - mn);
            s[i][1] = __expf(s[i][1] - mn);
            s[i][2] = __expf(s[i][2] - mn);
            s[i][3] = __expf(s[i][3] - mn);
            float rs = (s[i][0] + s[i][1]) + (s[i][2] + s[i][3]);
#pragma unroll
            for (int o = 8; o >= 1; o >>= 1)
                rs += __shfl_xor_sync(0xffffffffu, rs, o);
            l[i] = l[i] * alpha[i] + rs;
        }
        __syncthreads();   // S2: all K^T reads done before P overwrites U

        // write P
#pragma unroll
        for (int i = 0; i < 4; i++) {
            float4 pv = {s[i][0], s[i][1], s[i][2], s[i][3]};
            *(float4*)(U + (ty * 4 + i) * 64 + tx * 4) = pv;
        }
        __syncthreads();   // S3: P visible

        // Phase C: acc = acc*alpha + P * V, blocked by 4 k-cols
#pragma unroll
        for (int i = 0; i < 4; i++)
#pragma unroll
            for (int j = 0; j < 4; j++) acc[i][j] *= alpha[i];
#pragma unroll 4
        for (int j4 = 0; j4 < 16; j4++) {
            const float* Pb = U + (ty * 4) * 64 + j4 * 4;
            float4 p0 = *(const float4*)(Pb);
            float4 p1 = *(const float4*)(Pb + 64);
            float4 p2 = *(const float4*)(Pb + 128);
            float4 p3 = *(const float4*)(Pb + 192);
            float4 v0 = *(const float4*)(Vs + (j4 * 4 + 0) * 64 + tx * 4);
            float4 v1 = *(const float4*)(Vs + (j4 * 4 + 1) * 64 + tx * 4);
            float4 v2 = *(const float4*)(Vs + (j4 * 4 + 2) * 64 + tx * 4);
            float4 v3 = *(const float4*)(Vs + (j4 * 4 + 3) * 64 + tx * 4);
            PVROW(0, p0);
            PVROW(1, p1);
            PVROW(2, p2);
            PVROW(3, p3);
        }
        __syncthreads();   // S4: U/Vs consumed before next tile store
    }

    // Normalize and write merged [MROWS][HID]: col = h*64 + d
    {
        const int b = bh >> 4, hh = bh & 15;
#pragma unroll
        for (int i = 0; i < 4; i++) {
            float inv = 1.0f / l[i];
            float4 o;
            o.x = acc[i][0] * inv; o.y = acc[i][1] * inv;
            o.z = acc[i][2] * inv; o.w = acc[i][3] * inv;
            *(float4*)(g_M + (size_t)(b * SEQ + q0 + ty * 4 + i) * HID
                       + hh * DKDIM + tx * 4) = o;
        }
    }
}

// ---------------------------------------------------------------------------
extern "C" void kernel_launch(void* const* d_in, const int* in_sizes, int n_in,
                              void* d_out, int out_size) {
    const float* q  = (const float*)d_in[0];
    const float* k  = (const float*)d_in[1];
    const float* v  = (const float*)d_in[2];
    const float* Wq = (const float*)d_in[3];
    const float* bq = (const float*)d_in[4];
    const float* Wk = (const float*)d_in[5];
    const float* bk = (const float*)d_in[6];
    const float* Wv = (const float*)d_in[7];
    const float* bv = (const float*)d_in[8];
    const float* Wo = (const float*)d_in[9];
    const float* bo = (const float*)d_in[10];
    const float* Wc = (const float*)d_in[11];
    const float* bc = (const float*)d_in[12];
    float* out = (float*)d_out;

    dim3 g1(HID / GBN, MROWS / GBM, 3);
    qkv_gemm_kernel<<<g1, 256>>>(q, k, v, Wq, bq, Wk, bk, Wv, bv);

    attn_kernel<<<dim3(SEQ / 64, BATCH * NHEAD), 256>>>();

    dim3 g2(HID / GBN, MROWS / GBM, 2);
    out_gemm_kernel<<<g2, 256>>>(Wo, bo, Wc, bc, out);
}

// round 13
// speedup vs baseline: 1.0138x; 1.0138x over previous
#include <cuda_runtime.h>
#include <cstdint>

// Problem constants
#define HID   1024
#define NHEAD 16
#define DKDIM 64
#define SEQ   2048
#define BATCH 2
#define MROWS (BATCH * SEQ)      // 4096
#define HEADSZ (SEQ * DKDIM)     // 131072 floats per (b,h) head

// Scratch (allocation-free rule: __device__ globals)
__device__ float g_Q[MROWS * HID];   // head-major [B*NH][SEQ][DK]
__device__ float g_K[MROWS * HID];
__device__ float g_V[MROWS * HID];
__device__ float g_M[MROWS * HID];   // merged attention output [MROWS][HID]

// ---------------------------------------------------------------------------
// SGEMM: C[M,N] = A[M,K=1024] * W[1024,N] + bias
// 128x128 tile, GBK=16, register-staged double buffer, 1 sync per chunk.
// B fragments at {tx*4, 64+tx*4}: stride-4 => conflict-free LDS.128.
// A loader: R9 mapping (16 rows x 64B per warp: best global coalescing).
// Epilogue: float4 stores (columns consecutive in groups of 4).
// ---------------------------------------------------------------------------
#define GBM 128
#define GBN 128
#define GBK 16
#define NKCH (HID / GBK)   // 64

template<bool HEAD_MAJOR>
__device__ __forceinline__ void sgemm_tile(const float* __restrict__ A,
                                           const float* __restrict__ W,
                                           const float* __restrict__ bias,
                                           float* __restrict__ out, int N) {
    __shared__ float As[2][GBK][GBM];   // 16 KB
    __shared__ float Bs[2][GBK][GBN];   // 16 KB
    const int tid = threadIdx.x;
    const int tx = tid & 15, ty = tid >> 4;
    const int row0 = blockIdx.y * GBM;
    const int col0 = blockIdx.x * GBN;

    // A loader: row = tid/2, k-offset = (tid&1)*8, two float4s (R9 mapping)
    const int a_row = tid >> 1;
    const int a_k8  = (tid & 1) * 8;
    // B loader: k-row = tid/16 (0..15), n-offsets {b_n4, 64+b_n4}
    const int b_k  = tid >> 4;
    const int b_n4 = (tid & 15) * 4;

    const float* Aptr = A + (size_t)(row0 + a_row) * HID + a_k8;
    const float* Wptr = W + col0 + b_n4;   // + k*N per chunk

    float acc[8][8];
#pragma unroll
    for (int i = 0; i < 8; i++)
#pragma unroll
        for (int j = 0; j < 8; j++) acc[i][j] = 0.f;

    // preamble: chunk 0 -> smem[0]
    {
        float4 ra0 = *(const float4*)(Aptr + 0);
        float4 ra1 = *(const float4*)(Aptr + 4);
        float4 rb0 = *(const float4*)(Wptr + (size_t)b_k * N);
        float4 rb1 = *(const float4*)(Wptr + (size_t)b_k * N + 64);
        As[0][a_k8 + 0][a_row] = ra0.x; As[0][a_k8 + 1][a_row] = ra0.y;
        As[0][a_k8 + 2][a_row] = ra0.z; As[0][a_k8 + 3][a_row] = ra0.w;
        As[0][a_k8 + 4][a_row] = ra1.x; As[0][a_k8 + 5][a_row] = ra1.y;
        As[0][a_k8 + 6][a_row] = ra1.z; As[0][a_k8 + 7][a_row] = ra1.w;
        *(float4*)&Bs[0][b_k][b_n4]      = rb0;
        *(float4*)&Bs[0][b_k][b_n4 + 64] = rb1;
    }
    __syncthreads();

    for (int c = 0; c < NKCH; c++) {
        const int buf = c & 1;
        float4 ra0, ra1, rb0, rb1;
        const bool more = (c + 1 < NKCH);
        if (more) {
            const int k0 = (c + 1) * GBK;
            ra0 = *(const float4*)(Aptr + k0);
            ra1 = *(const float4*)(Aptr + k0 + 4);
            rb0 = *(const float4*)(Wptr + (size_t)(k0 + b_k) * N);
            rb1 = *(const float4*)(Wptr + (size_t)(k0 + b_k) * N + 64);
        }
#pragma unroll
        for (int k = 0; k < GBK; k++) {
            float4 a0 = *(const float4*)&As[buf][k][ty * 8];
            float4 a1 = *(const float4*)&As[buf][k][ty * 8 + 4];
            float4 b0 = *(const float4*)&Bs[buf][k][tx * 4];
            float4 b1 = *(const float4*)&Bs[buf][k][64 + tx * 4];
            float ra[8] = {a0.x, a0.y, a0.z, a0.w, a1.x, a1.y, a1.z, a1.w};
            float rb[8] = {b0.x, b0.y, b0.z, b0.w, b1.x, b1.y, b1.z, b1.w};
#pragma unroll
            for (int i = 0; i < 8; i++)
#pragma unroll
                for (int j = 0; j < 8; j++)
                    acc[i][j] = fmaf(ra[i], rb[j], acc[i][j]);
        }
        if (more) {
            const int nb = buf ^ 1;
            As[nb][a_k8 + 0][a_row] = ra0.x; As[nb][a_k8 + 1][a_row] = ra0.y;
            As[nb][a_k8 + 2][a_row] = ra0.z; As[nb][a_k8 + 3][a_row] = ra0.w;
            As[nb][a_k8 + 4][a_row] = ra1.x; As[nb][a_k8 + 5][a_row] = ra1.y;
            As[nb][a_k8 + 6][a_row] = ra1.z; As[nb][a_k8 + 7][a_row] = ra1.w;
            *(float4*)&Bs[nb][b_k][b_n4]      = rb0;
            *(float4*)&Bs[nb][b_k][b_n4 + 64] = rb1;
            __syncthreads();
        }
    }

    // epilogue: two float4 stores per row (n groups {tx*4, 64+tx*4})
    const float4 bb0 = *(const float4*)(bias + col0 + tx * 4);
    const float4 bb1 = *(const float4*)(bias + col0 + 64 + tx * 4);
#pragma unroll
    for (int i = 0; i < 8; i++) {
        int mrow = row0 + ty * 8 + i;
        float4 v0 = {acc[i][0] + bb0.x, acc[i][1] + bb0.y,
                     acc[i][2] + bb0.z, acc[i][3] + bb0.w};
        float4 v1 = {acc[i][4] + bb1.x, acc[i][5] + bb1.y,
                     acc[i][6] + bb1.z, acc[i][7] + bb1.w};
        if (HEAD_MAJOR) {
            int b = mrow >> 11, s = mrow & 2047;          // SEQ = 2048
            int n0 = col0 + tx * 4;                        // group 0
            int h0 = n0 >> 6, d0 = n0 & 63;
            *(float4*)(out + (((size_t)((b << 4) + h0)) << 17)
                       + ((size_t)s << 6) + d0) = v0;
            int n1 = col0 + 64 + tx * 4;                   // group 1
            int h1 = n1 >> 6, d1 = n1 & 63;
            *(float4*)(out + (((size_t)((b << 4) + h1)) << 17)
                       + ((size_t)s << 6) + d1) = v1;
        } else {
            *(float4*)(out + (size_t)mrow * N + col0 + tx * 4) = v0;
            *(float4*)(out + (size_t)mrow * N + col0 + 64 + tx * 4) = v1;
        }
    }
}

__global__ __launch_bounds__(256, 2) void qkv_gemm_kernel(
    const float* q, const float* k, const float* v,
    const float* Wq, const float* bq,
    const float* Wk, const float* bk,
    const float* Wv, const float* bv) {
    const float *A, *W, *bias;
    float* out;
    if (blockIdx.z == 0)      { A = q; W = Wq; bias = bq; out = g_Q; }
    else if (blockIdx.z == 1) { A = k; W = Wk; bias = bk; out = g_K; }
    else                      { A = v; W = Wv; bias = bv; out = g_V; }
    sgemm_tile<true>(A, W, bias, out, HID);
}

__global__ __launch_bounds__(256, 2) void out_gemm_kernel(
    const float* Wo, const float* bo,
    const float* Wc, const float* bc, float* out) {
    const float *W, *bias;
    float* o;
    if (blockIdx.z == 0) { W = Wc; bias = bc; o = out; }                        // c first
    else                 { W = Wo; bias = bo; o = out + (size_t)MROWS * HID; }  // then h
    sgemm_tile<false>(g_M, W, bias, o, HID);
}

// ---------------------------------------------------------------------------
// Flash attention, 64q x 64k tiles. 256 threads = (tx=16, ty=16).
// Scores 4q x 4k in registers; softmax via shfl_xor; P through smem (U).
// Phase C blocked by 4 k-cols: float4 P + float4 V loads, 64 FMA per block.
// ---------------------------------------------------------------------------
#define PVROW(i, pp) do { \
    acc[i][0] = fmaf(pp.x, v0.x, acc[i][0]); acc[i][0] = fmaf(pp.y, v1.x, acc[i][0]); \
    acc[i][0] = fmaf(pp.z, v2.x, acc[i][0]); acc[i][0] = fmaf(pp.w, v3.x, acc[i][0]); \
    acc[i][1] = fmaf(pp.x, v0.y, acc[i][1]); acc[i][1] = fmaf(pp.y, v1.y, acc[i][1]); \
    acc[i][1] = fmaf(pp.z, v2.y, acc[i][1]); acc[i][1] = fmaf(pp.w, v3.y, acc[i][1]); \
    acc[i][2] = fmaf(pp.x, v0.z, acc[i][2]); acc[i][2] = fmaf(pp.y, v1.z, acc[i][2]); \
    acc[i][2] = fmaf(pp.z, v2.z, acc[i][2]); acc[i][2] = fmaf(pp.w, v3.z, acc[i][2]); \
    acc[i][3] = fmaf(pp.x, v0.w, acc[i][3]); acc[i][3] = fmaf(pp.y, v1.w, acc[i][3]); \
    acc[i][3] = fmaf(pp.z, v2.w, acc[i][3]); acc[i][3] = fmaf(pp.w, v3.w, acc[i][3]); \
} while (0)

__global__ __launch_bounds__(256) void attn_kernel() {
    __shared__ float QsT[64 * 64];   // [d][q]
    __shared__ float U[64 * 64];     // K^T [d][k] -> P [q][k]
    __shared__ float Vs[64 * 64];    // [k][d]

    const int bh = blockIdx.y;
    const int q0 = blockIdx.x * 64;
    const float* Qh = g_Q + (size_t)bh * HEADSZ;
    const float* Kh = g_K + (size_t)bh * HEADSZ;
    const float* Vh = g_V + (size_t)bh * HEADSZ;
    const int tid = threadIdx.x;
    const int tx = tid & 15, ty = tid >> 4;

    // Load Q transposed + scaled. idx -> (q = idx&63, d4 = (idx>>6)*4)
#pragma unroll
    for (int t = 0; t < 4; t++) {
        int idx = tid + t * 256;
        int r = idx & 63, c4 = (idx >> 6) << 2;
        float4 v = *(const float4*)(Qh + (size_t)(q0 + r) * DKDIM + c4);
        QsT[(c4 + 0) * 64 + r] = v.x * 0.125f;
        QsT[(c4 + 1) * 64 + r] = v.y * 0.125f;
        QsT[(c4 + 2) * 64 + r] = v.z * 0.125f;
        QsT[(c4 + 3) * 64 + r] = v.w * 0.125f;
    }

    float m[4], l[4], acc[4][4];
#pragma unroll
    for (int i = 0; i < 4; i++) {
        m[i] = -1e30f; l[i] = 0.f;
#pragma unroll
        for (int j = 0; j < 4; j++) acc[i][j] = 0.f;
    }

    // prefetch tile 0 into regs: K via transpose mapping, V coalesced
    float4 kreg[4], vreg[4];
#pragma unroll
    for (int t = 0; t < 4; t++) {
        int idx = tid + t * 256;
        int rk = idx & 63, ck = (idx >> 6) << 2;
        kreg[t] = *(const float4*)(Kh + (size_t)rk * DKDIM + ck);
        int rv = idx >> 4, cv = (idx & 15) << 2;
        vreg[t] = *(const float4*)(Vh + (size_t)rv * DKDIM + cv);
    }
    __syncthreads();   // QsT visible

    for (int c = 0; c < SEQ / 64; c++) {
        // store prefetched K (transposed) and V
#pragma unroll
        for (int t = 0; t < 4; t++) {
            int idx = tid + t * 256;
            int rk = idx & 63, ck = (idx >> 6) << 2;
            U[(ck + 0) * 64 + rk] = kreg[t].x;
            U[(ck + 1) * 64 + rk] = kreg[t].y;
            U[(ck + 2) * 64 + rk] = kreg[t].z;
            U[(ck + 3) * 64 + rk] = kreg[t].w;
            int rv = idx >> 4, cv = (idx & 15) << 2;
            *(float4*)(Vs + rv * 64 + cv) = vreg[t];
        }
        __syncthreads();   // S1: tiles visible

        if (c + 1 < SEQ / 64) {
            const int k0 = (c + 1) * 64;
#pragma unroll
            for (int t = 0; t < 4; t++) {
                int idx = tid + t * 256;
                int rk = idx & 63, ck = (idx >> 6) << 2;
                kreg[t] = *(const float4*)(Kh + (size_t)(k0 + rk) * DKDIM + ck);
                int rv = idx >> 4, cv = (idx & 15) << 2;
                vreg[t] = *(const float4*)(Vh + (size_t)(k0 + rv) * DKDIM + cv);
            }
        }

        // Phase A: scores (4q x 4k) in registers
        float s[4][4];
#pragma unroll
        for (int i = 0; i < 4; i++)
#pragma unroll
            for (int j = 0; j < 4; j++) s[i][j] = 0.f;
#pragma unroll 8
        for (int d = 0; d < 64; d++) {
            float4 qv = *(const float4*)(QsT + d * 64 + ty * 4);
            float4 kv = *(const float4*)(U + d * 64 + tx * 4);
            s[0][0] = fmaf(qv.x, kv.x, s[0][0]); s[0][1] = fmaf(qv.x, kv.y, s[0][1]);
            s[0][2] = fmaf(qv.x, kv.z, s[0][2]); s[0][3] = fmaf(qv.x, kv.w, s[0][3]);
            s[1][0] = fmaf(qv.y, kv.x, s[1][0]); s[1][1] = fmaf(qv.y, kv.y, s[1][1]);
            s[1][2] = fmaf(qv.y, kv.z, s[1][2]); s[1][3] = fmaf(qv.y, kv.w, s[1][3]);
            s[2][0] = fmaf(qv.z, kv.x, s[2][0]); s[2][1] = fmaf(qv.z, kv.y, s[2][1]);
            s[2][2] = fmaf(qv.z, kv.z, s[2][2]); s[2][3] = fmaf(qv.z, kv.w, s[2][3]);
            s[3][0] = fmaf(qv.w, kv.x, s[3][0]); s[3][1] = fmaf(qv.w, kv.y, s[3][1]);
            s[3][2] = fmaf(qv.w, kv.z, s[3][2]); s[3][3] = fmaf(qv.w, kv.w, s[3][3]);
        }

        // Online softmax in registers (replicated across tx via shuffles)
        float alpha[4];
#pragma unroll
        for (int i = 0; i < 4; i++) {
            float rm = fmaxf(fmaxf(s[i][0], s[i][1]), fmaxf(s[i][2], s[i][3]));
#pragma unroll
            for (int o = 8; o >= 1; o >>= 1)
                rm = fmaxf(rm, __shfl_xor_sync(0xffffffffu, rm, o));
            float mn = fmaxf(m[i], rm);
            alpha[i] = __expf(m[i] - mn);
            m[i] = mn;
            s[i][0] = __expf(s[i][0] - mn);
            s[i][1] = __expf(s[i][1] - mn);
            s[i][2] = __expf(s[i][2] - mn);
            s[i][3] = __expf(s[i][3] - mn);
            float rs = (s[i][0] + s[i][1]) + (s[i][2] + s[i][3]);
#pragma unroll
            for (int o = 8; o >= 1; o >>= 1)
                rs += __shfl_xor_sync(0xffffffffu, rs, o);
            l[i] = l[i] * alpha[i] + rs;
        }
        __syncthreads();   // S2: all K^T reads done before P overwrites U

        // write P
#pragma unroll
        for (int i = 0; i < 4; i++) {
            float4 pv = {s[i][0], s[i][1], s[i][2], s[i][3]};
            *(float4*)(U + (ty * 4 + i) * 64 + tx * 4) = pv;
        }
        __syncthreads();   // S3: P visible

        // Phase C: acc = acc*alpha + P * V, blocked by 4 k-cols
#pragma unroll
        for (int i = 0; i < 4; i++)
#pragma unroll
            for (int j = 0; j < 4; j++) acc[i][j] *= alpha[i];
#pragma unroll 4
        for (int j4 = 0; j4 < 16; j4++) {
            const float* Pb = U + (ty * 4) * 64 + j4 * 4;
            float4 p0 = *(const float4*)(Pb);
            float4 p1 = *(const float4*)(Pb + 64);
            float4 p2 = *(const float4*)(Pb + 128);
            float4 p3 = *(const float4*)(Pb + 192);
            float4 v0 = *(const float4*)(Vs + (j4 * 4 + 0) * 64 + tx * 4);
            float4 v1 = *(const float4*)(Vs + (j4 * 4 + 1) * 64 + tx * 4);
            float4 v2 = *(const float4*)(Vs + (j4 * 4 + 2) * 64 + tx * 4);
            float4 v3 = *(const float4*)(Vs + (j4 * 4 + 3) * 64 + tx * 4);
            PVROW(0, p0);
            PVROW(1, p1);
            PVROW(2, p2);
            PVROW(3, p3);
        }
        __syncthreads();   // S4: U/Vs consumed before next tile store
    }

    // Normalize and write merged [MROWS][HID]: col = h*64 + d
    {
        const int b = bh >> 4, hh = bh & 15;
#pragma unroll
        for (int i = 0; i < 4; i++) {
            float inv = 1.0f / l[i];
            float4 o;
            o.x = acc[i][0] * inv; o.y = acc[i][1] * inv;
            o.z = acc[i][2] * inv; o.w = acc[i][3] * inv;
            *(float4*)(g_M + (size_t)(b * SEQ + q0 + ty * 4 + i) * HID
                       + hh * DKDIM + tx * 4) = o;
        }
    }
}

// ---------------------------------------------------------------------------
extern "C" void kernel_launch(void* const* d_in, const int* in_sizes, int n_in,
                              void* d_out, int out_size) {
    const float* q  = (const float*)d_in[0];
    const float* k  = (const float*)d_in[1];
    const float* v  = (const float*)d_in[2];
    const float* Wq = (const float*)d_in[3];
    const float* bq = (const float*)d_in[4];
    const float* Wk = (const float*)d_in[5];
    const float* bk = (const float*)d_in[6];
    const float* Wv = (const float*)d_in[7];
    const float* bv = (const float*)d_in[8];
    const float* Wo = (const float*)d_in[9];
    const float* bo = (const float*)d_in[10];
    const float* Wc = (const float*)d_in[11];
    const float* bc = (const float*)d_in[12];
    float* out = (float*)d_out;

    dim3 g1(HID / GBN, MROWS / GBM, 3);
    qkv_gemm_kernel<<<g1, 256>>>(q, k, v, Wq, bq, Wk, bk, Wv, bv);

    attn_kernel<<<dim3(SEQ / 64, BATCH * NHEAD), 256>>>();

    dim3 g2(HID / GBN, MROWS / GBM, 2);
    out_gemm_kernel<<<g2, 256>>>(Wo, bo, Wc, bc, out);
}

// round 17
// speedup vs baseline: 1.0380x; 1.0238x over previous
#include <cuda_runtime.h>
#include <cstdint>

// Problem constants
#define HID   1024
#define NHEAD 16
#define DKDIM 64
#define SEQ   2048
#define BATCH 2
#define MROWS (BATCH * SEQ)      // 4096
#define HEADSZ (SEQ * DKDIM)     // 131072 floats per (b,h) head

// Scratch (allocation-free rule: __device__ globals)
__device__ float g_Q[MROWS * HID];   // head-major [B*NH][SEQ][DK]
__device__ float g_K[MROWS * HID];
__device__ float g_V[MROWS * HID];
__device__ float g_M[MROWS * HID];   // merged attention output [MROWS][HID]

// ---------------------------------------------------------------------------
// SGEMM: C[M,N] = A[M,K=1024] * W[1024,N] + bias
// 128x128 tile, GBK=16, register-staged double buffer (global) +
// register double-buffered fragments (smem) => LDS latency hidden.
// ---------------------------------------------------------------------------
#define GBM 128
#define GBN 128
#define GBK 16
#define NKCH (HID / GBK)   // 64

#define FMA64(A0, A1, B0, B1) do {                                            \
    float ra[8] = {A0.x, A0.y, A0.z, A0.w, A1.x, A1.y, A1.z, A1.w};           \
    float rb[8] = {B0.x, B0.y, B0.z, B0.w, B1.x, B1.y, B1.z, B1.w};           \
    _Pragma("unroll")                                                         \
    for (int i = 0; i < 8; i++)                                               \
        _Pragma("unroll")                                                     \
        for (int j = 0; j < 8; j++)                                           \
            acc[i][j] = fmaf(ra[i], rb[j], acc[i][j]);                        \
} while (0)

template<bool HEAD_MAJOR>
__device__ __forceinline__ void sgemm_tile(const float* __restrict__ A,
                                           const float* __restrict__ W,
                                           const float* __restrict__ bias,
                                           float* __restrict__ out, int N) {
    __shared__ float As[2][GBK][GBM];   // 16 KB
    __shared__ float Bs[2][GBK][GBN];   // 16 KB
    const int tid = threadIdx.x;
    const int tx = tid & 15, ty = tid >> 4;
    const int row0 = blockIdx.y * GBM;
    const int col0 = blockIdx.x * GBN;

    // A loader: row = tid/2, k-offset = (tid&1)*8, two float4s
    const int a_row = tid >> 1;
    const int a_k8  = (tid & 1) * 8;
    // B loader: k-row = tid/16 (0..15), n-offsets {b_n4, 64+b_n4}
    const int b_k  = tid >> 4;
    const int b_n4 = (tid & 15) * 4;

    const float* Aptr = A + (size_t)(row0 + a_row) * HID + a_k8;
    const float* Wptr = W + col0 + b_n4;   // + k*N per chunk

    float acc[8][8];
#pragma unroll
    for (int i = 0; i < 8; i++)
#pragma unroll
        for (int j = 0; j < 8; j++) acc[i][j] = 0.f;

    // preamble: chunk 0 -> smem[0]
    {
        float4 ra0 = *(const float4*)(Aptr + 0);
        float4 ra1 = *(const float4*)(Aptr + 4);
        float4 rb0 = *(const float4*)(Wptr + (size_t)b_k * N);
        float4 rb1 = *(const float4*)(Wptr + (size_t)b_k * N + 64);
        As[0][a_k8 + 0][a_row] = ra0.x; As[0][a_k8 + 1][a_row] = ra0.y;
        As[0][a_k8 + 2][a_row] = ra0.z; As[0][a_k8 + 3][a_row] = ra0.w;
        As[0][a_k8 + 4][a_row] = ra1.x; As[0][a_k8 + 5][a_row] = ra1.y;
        As[0][a_k8 + 6][a_row] = ra1.z; As[0][a_k8 + 7][a_row] = ra1.w;
        *(float4*)&Bs[0][b_k][b_n4]      = rb0;
        *(float4*)&Bs[0][b_k][b_n4 + 64] = rb1;
    }
    __syncthreads();

    for (int c = 0; c < NKCH; c++) {
        const int buf = c & 1;
        float4 ra0, ra1, rb0, rb1;
        const bool more = (c + 1 < NKCH);
        if (more) {
            const int k0 = (c + 1) * GBK;
            ra0 = *(const float4*)(Aptr + k0);
            ra1 = *(const float4*)(Aptr + k0 + 4);
            rb0 = *(const float4*)(Wptr + (size_t)(k0 + b_k) * N);
            rb1 = *(const float4*)(Wptr + (size_t)(k0 + b_k) * N + 64);
        }
        // inner loop: fragment double-buffer hides LDS latency
        {
            float4 fa0[2], fa1[2], fb0[2], fb1[2];
            fa0[0] = *(const float4*)&As[buf][0][ty * 8];
            fa1[0] = *(const float4*)&As[buf][0][ty * 8 + 4];
            fb0[0] = *(const float4*)&Bs[buf][0][tx * 4];
            fb1[0] = *(const float4*)&Bs[buf][0][64 + tx * 4];
#pragma unroll
            for (int k = 0; k < GBK; k++) {
                const int cur = k & 1, nxt = cur ^ 1;
                if (k + 1 < GBK) {
                    fa0[nxt] = *(const float4*)&As[buf][k + 1][ty * 8];
                    fa1[nxt] = *(const float4*)&As[buf][k + 1][ty * 8 + 4];
                    fb0[nxt] = *(const float4*)&Bs[buf][k + 1][tx * 4];
                    fb1[nxt] = *(const float4*)&Bs[buf][k + 1][64 + tx * 4];
                }
                FMA64(fa0[cur], fa1[cur], fb0[cur], fb1[cur]);
            }
        }
        if (more) {
            const int nb = buf ^ 1;
            As[nb][a_k8 + 0][a_row] = ra0.x; As[nb][a_k8 + 1][a_row] = ra0.y;
            As[nb][a_k8 + 2][a_row] = ra0.z; As[nb][a_k8 + 3][a_row] = ra0.w;
            As[nb][a_k8 + 4][a_row] = ra1.x; As[nb][a_k8 + 5][a_row] = ra1.y;
            As[nb][a_k8 + 6][a_row] = ra1.z; As[nb][a_k8 + 7][a_row] = ra1.w;
            *(float4*)&Bs[nb][b_k][b_n4]      = rb0;
            *(float4*)&Bs[nb][b_k][b_n4 + 64] = rb1;
            __syncthreads();
        }
    }

    // epilogue: two float4 stores per row (n groups {tx*4, 64+tx*4})
    const float4 bb0 = *(const float4*)(bias + col0 + tx * 4);
    const float4 bb1 = *(const float4*)(bias + col0 + 64 + tx * 4);
#pragma unroll
    for (int i = 0; i < 8; i++) {
        int mrow = row0 + ty * 8 + i;
        float4 v0 = {acc[i][0] + bb0.x, acc[i][1] + bb0.y,
                     acc[i][2] + bb0.z, acc[i][3] + bb0.w};
        float4 v1 = {acc[i][4] + bb1.x, acc[i][5] + bb1.y,
                     acc[i][6] + bb1.z, acc[i][7] + bb1.w};
        if (HEAD_MAJOR) {
            int b = mrow >> 11, s = mrow & 2047;          // SEQ = 2048
            int n0 = col0 + tx * 4;                        // group 0
            int h0 = n0 >> 6, d0 = n0 & 63;
            *(float4*)(out + (((size_t)((b << 4) + h0)) << 17)
                       + ((size_t)s << 6) + d0) = v0;
            int n1 = col0 + 64 + tx * 4;                   // group 1
            int h1 = n1 >> 6, d1 = n1 & 63;
            *(float4*)(out + (((size_t)((b << 4) + h1)) << 17)
                       + ((size_t)s << 6) + d1) = v1;
        } else {
            *(float4*)(out + (size_t)mrow * N + col0 + tx * 4) = v0;
            *(float4*)(out + (size_t)mrow * N + col0 + 64 + tx * 4) = v1;
        }
    }
}

__global__ __launch_bounds__(256, 2) void qkv_gemm_kernel(
    const float* q, const float* k, const float* v,
    const float* Wq, const float* bq,
    const float* Wk, const float* bk,
    const float* Wv, const float* bv) {
    const float *A, *W, *bias;
    float* out;
    if (blockIdx.z == 0)      { A = q; W = Wq; bias = bq; out = g_Q; }
    else if (blockIdx.z == 1) { A = k; W = Wk; bias = bk; out = g_K; }
    else                      { A = v; W = Wv; bias = bv; out = g_V; }
    sgemm_tile<true>(A, W, bias, out, HID);
}

__global__ __launch_bounds__(256, 2) void out_gemm_kernel(
    const float* Wo, const float* bo,
    const float* Wc, const float* bc, float* out) {
    const float *W, *bias;
    float* o;
    if (blockIdx.z == 0) { W = Wc; bias = bc; o = out; }                        // c first
    else                 { W = Wo; bias = bo; o = out + (size_t)MROWS * HID; }  // then h
    sgemm_tile<false>(g_M, W, bias, o, HID);
}

// ---------------------------------------------------------------------------
// Flash attention, 64q x 64k tiles. 256 threads = (tx=16, ty=16).
// Scores 4q x 4k in registers; softmax via shfl_xor; P through smem (U).
// Phase C blocked by 4 k-cols: float4 P + float4 V loads, 64 FMA per block.
// ---------------------------------------------------------------------------
#define PVROW(i, pp) do { \
    acc[i][0] = fmaf(pp.x, v0.x, acc[i][0]); acc[i][0] = fmaf(pp.y, v1.x, acc[i][0]); \
    acc[i][0] = fmaf(pp.z, v2.x, acc[i][0]); acc[i][0] = fmaf(pp.w, v3.x, acc[i][0]); \
    acc[i][1] = fmaf(pp.x, v0.y, acc[i][1]); acc[i][1] = fmaf(pp.y, v1.y, acc[i][1]); \
    acc[i][1] = fmaf(pp.z, v2.y, acc[i][1]); acc[i][1] = fmaf(pp.w, v3.y, acc[i][1]); \
    acc[i][2] = fmaf(pp.x, v0.z, acc[i][2]); acc[i][2] = fmaf(pp.y, v1.z, acc[i][2]); \
    acc[i][2] = fmaf(pp.z, v2.z, acc[i][2]); acc[i][2] = fmaf(pp.w, v3.z, acc[i][2]); \
    acc[i][3] = fmaf(pp.x, v0.w, acc[i][3]); acc[i][3] = fmaf(pp.y, v1.w, acc[i][3]); \
    acc[i][3] = fmaf(pp.z, v2.w, acc[i][3]); acc[i][3] = fmaf(pp.w, v3.w, acc[i][3]); \
} while (0)

__global__ __launch_bounds__(256) void attn_kernel() {
    __shared__ float QsT[64 * 64];   // [d][q]
    __shared__ float U[64 * 64];     // K^T [d][k] -> P [q][k]
    __shared__ float Vs[64 * 64];    // [k][d]

    const int bh = blockIdx.y;
    const int q0 = blockIdx.x * 64;
    const float* Qh = g_Q + (size_t)bh * HEADSZ;
    const float* Kh = g_K + (size_t)bh * HEADSZ;
    const float* Vh = g_V + (size_t)bh * HEADSZ;
    const int tid = threadIdx.x;
    const int tx = tid & 15, ty = tid >> 4;

    // Load Q transposed + scaled. idx -> (q = idx&63, d4 = (idx>>6)*4)
#pragma unroll
    for (int t = 0; t < 4; t++) {
        int idx = tid + t * 256;
        int r = idx & 63, c4 = (idx >> 6) << 2;
        float4 v = *(const float4*)(Qh + (size_t)(q0 + r) * DKDIM + c4);
        QsT[(c4 + 0) * 64 + r] = v.x * 0.125f;
        QsT[(c4 + 1) * 64 + r] = v.y * 0.125f;
        QsT[(c4 + 2) * 64 + r] = v.z * 0.125f;
        QsT[(c4 + 3) * 64 + r] = v.w * 0.125f;
    }

    float m[4], l[4], acc[4][4];
#pragma unroll
    for (int i = 0; i < 4; i++) {
        m[i] = -1e30f; l[i] = 0.f;
#pragma unroll
        for (int j = 0; j < 4; j++) acc[i][j] = 0.f;
    }

    // prefetch tile 0 into regs: K via transpose mapping, V coalesced
    float4 kreg[4], vreg[4];
#pragma unroll
    for (int t = 0; t < 4; t++) {
        int idx = tid + t * 256;
        int rk = idx & 63, ck = (idx >> 6) << 2;
        kreg[t] = *(const float4*)(Kh + (size_t)rk * DKDIM + ck);
        int rv = idx >> 4, cv = (idx & 15) << 2;
        vreg[t] = *(const float4*)(Vh + (size_t)rv * DKDIM + cv);
    }
    __syncthreads();   // QsT visible

    for (int c = 0; c < SEQ / 64; c++) {
        // store prefetched K (transposed) and V
#pragma unroll
        for (int t = 0; t < 4; t++) {
            int idx = tid + t * 256;
            int rk = idx & 63, ck = (idx >> 6) << 2;
            U[(ck + 0) * 64 + rk] = kreg[t].x;
            U[(ck + 1) * 64 + rk] = kreg[t].y;
            U[(ck + 2) * 64 + rk] = kreg[t].z;
            U[(ck + 3) * 64 + rk] = kreg[t].w;
            int rv = idx >> 4, cv = (idx & 15) << 2;
            *(float4*)(Vs + rv * 64 + cv) = vreg[t];
        }
        __syncthreads();   // S1: tiles visible

        if (c + 1 < SEQ / 64) {
            const int k0 = (c + 1) * 64;
#pragma unroll
            for (int t = 0; t < 4; t++) {
                int idx = tid + t * 256;
                int rk = idx & 63, ck = (idx >> 6) << 2;
                kreg[t] = *(const float4*)(Kh + (size_t)(k0 + rk) * DKDIM + ck);
                int rv = idx >> 4, cv = (idx & 15) << 2;
                vreg[t] = *(const float4*)(Vh + (size_t)(k0 + rv) * DKDIM + cv);
            }
        }

        // Phase A: scores (4q x 4k) in registers
        float s[4][4];
#pragma unroll
        for (int i = 0; i < 4; i++)
#pragma unroll
            for (int j = 0; j < 4; j++) s[i][j] = 0.f;
#pragma unroll 8
        for (int d = 0; d < 64; d++) {
            float4 qv = *(const float4*)(QsT + d * 64 + ty * 4);
            float4 kv = *(const float4*)(U + d * 64 + tx * 4);
            s[0][0] = fmaf(qv.x, kv.x, s[0][0]); s[0][1] = fmaf(qv.x, kv.y, s[0][1]);
            s[0][2] = fmaf(qv.x, kv.z, s[0][2]); s[0][3] = fmaf(qv.x, kv.w, s[0][3]);
            s[1][0] = fmaf(qv.y, kv.x, s[1][0]); s[1][1] = fmaf(qv.y, kv.y, s[1][1]);
            s[1][2] = fmaf(qv.y, kv.z, s[1][2]); s[1][3] = fmaf(qv.y, kv.w, s[1][3]);
            s[2][0] = fmaf(qv.z, kv.x, s[2][0]); s[2][1] = fmaf(qv.z, kv.y, s[2][1]);
            s[2][2] = fmaf(qv.z, kv.z, s[2][2]); s[2][3] = fmaf(qv.z, kv.w, s[2][3]);
            s[3][0] = fmaf(qv.w, kv.x, s[3][0]); s[3][1] = fmaf(qv.w, kv.y, s[3][1]);
            s[3][2] = fmaf(qv.w, kv.z, s[3][2]); s[3][3] = fmaf(qv.w, kv.w, s[3][3]);
        }

        // Online softmax in registers (replicated across tx via shuffles)
        float alpha[4];
#pragma unroll
        for (int i = 0; i < 4; i++) {
            float rm = fmaxf(fmaxf(s[i][0], s[i][1]), fmaxf(s[i][2], s[i][3]));
#pragma unroll
            for (int o = 8; o >= 1; o >>= 1)
                rm = fmaxf(rm, __shfl_xor_sync(0xffffffffu, rm, o));
            float mn = fmaxf(m[i], rm);
            alpha[i] = __expf(m[i] - mn);
            m[i] = mn;
            s[i][0] = __expf(s[i][0] - mn);
            s[i][1] = __expf(s[i][1] - mn);
            s[i][2] = __expf(s[i][2] - mn);
            s[i][3] = __expf(s[i][3] - mn);
            float rs = (s[i][0] + s[i][1]) + (s[i][2] + s[i][3]);
#pragma unroll
            for (int o = 8; o >= 1; o >>= 1)
                rs += __shfl_xor_sync(0xffffffffu, rs, o);
            l[i] = l[i] * alpha[i] + rs;
        }
        __syncthreads();   // S2: all K^T reads done before P overwrites U

        // write P
#pragma unroll
        for (int i = 0; i < 4; i++) {
            float4 pv = {s[i][0], s[i][1], s[i][2], s[i][3]};
            *(float4*)(U + (ty * 4 + i) * 64 + tx * 4) = pv;
        }
        __syncthreads();   // S3: P visible

        // Phase C: acc = acc*alpha + P * V, blocked by 4 k-cols
#pragma unroll
        for (int i = 0; i < 4; i++)
#pragma unroll
            for (int j = 0; j < 4; j++) acc[i][j] *= alpha[i];
#pragma unroll 4
        for (int j4 = 0; j4 < 16; j4++) {
            const float* Pb = U + (ty * 4) * 64 + j4 * 4;
            float4 p0 = *(const float4*)(Pb);
            float4 p1 = *(const float4*)(Pb + 64);
            float4 p2 = *(const float4*)(Pb + 128);
            float4 p3 = *(const float4*)(Pb + 192);
            float4 v0 = *(const float4*)(Vs + (j4 * 4 + 0) * 64 + tx * 4);
            float4 v1 = *(const float4*)(Vs + (j4 * 4 + 1) * 64 + tx * 4);
            float4 v2 = *(const float4*)(Vs + (j4 * 4 + 2) * 64 + tx * 4);
            float4 v3 = *(const float4*)(Vs + (j4 * 4 + 3) * 64 + tx * 4);
            PVROW(0, p0);
            PVROW(1, p1);
            PVROW(2, p2);
            PVROW(3, p3);
        }
        __syncthreads();   // S4: U/Vs consumed before next tile store
    }

    // Normalize and write merged [MROWS][HID]: col = h*64 + d
    {
        const int b = bh >> 4, hh = bh & 15;
#pragma unroll
        for (int i = 0; i < 4; i++) {
            float inv = 1.0f / l[i];
            float4 o;
            o.x = acc[i][0] * inv; o.y = acc[i][1] * inv;
            o.z = acc[i][2] * inv; o.w = acc[i][3] * inv;
            *(float4*)(g_M + (size_t)(b * SEQ + q0 + ty * 4 + i) * HID
                       + hh * DKDIM + tx * 4) = o;
        }
    }
}

// ---------------------------------------------------------------------------
extern "C" void kernel_launch(void* const* d_in, const int* in_sizes, int n_in,
                              void* d_out, int out_size) {
    const float* q  = (const float*)d_in[0];
    const float* k  = (const float*)d_in[1];
    const float* v  = (const float*)d_in[2];
    const float* Wq = (const float*)d_in[3];
    const float* bq = (const float*)d_in[4];
    const float* Wk = (const float*)d_in[5];
    const float* bk = (const float*)d_in[6];
    const float* Wv = (const float*)d_in[7];
    const float* bv = (const float*)d_in[8];
    const float* Wo = (const float*)d_in[9];
    const float* bo = (const float*)d_in[10];
    const float* Wc = (const float*)d_in[11];
    const float* bc = (const float*)d_in[12];
    float* out = (float*)d_out;

    dim3 g1(HID / GBN, MROWS / GBM, 3);
    qkv_gemm_kernel<<<g1, 256>>>(q, k, v, Wq, bq, Wk, bk, Wv, bv);

    attn_kernel<<<dim3(SEQ / 64, BATCH * NHEAD), 256>>>();

    dim3 g2(HID / GBN, MROWS / GBM, 2);
    out_gemm_kernel<<<g2, 256>>>(Wo, bo, Wc, bc, out);
}